// round 1
// baseline (speedup 1.0000x reference)
#include <cuda_runtime.h>
#include <cstdint>

// Problem constants (fixed by the dataset)
#define B_   4096
#define NM_  25
#define C_   64
#define NNZ_ 1000
#define NW_  55

#define BPB   8          // batches per block (one warp each)
#define THR   256        // 8 warps
#define GRID  (B_ / BPB) // 512

// Shared memory layout (floats):
//  s_x1 : BPB * NM_*C_  = 8*1600 = 12800
//  s_x2 : 12800
//  s_w  : BPB * NW_*C_  = 8*3520 = 28160
//  s_pk : NNZ_ u32  (as floats-worth of space: 1000)
//  s_cg : NNZ_ floats
#define SM_X1   0
#define SM_X2   (SM_X1 + BPB*NM_*C_)
#define SM_W    (SM_X2 + BPB*NM_*C_)
#define SM_PK   (SM_W  + BPB*NW_*C_)
#define SM_CG   (SM_PK + NNZ_)
#define SM_FLOATS (SM_CG + NNZ_)
#define SM_BYTES  (SM_FLOATS * 4)

__global__ __launch_bounds__(THR, 1)
void wtp_kernel(const float* __restrict__ x1,
                const float* __restrict__ x2,
                const float* __restrict__ wgt,
                const float* __restrict__ cg,
                const int* __restrict__ Mo,
                const int* __restrict__ M1,
                const int* __restrict__ M2,
                const int* __restrict__ Li,
                float* __restrict__ out)
{
    extern __shared__ float smem[];
    float* s_x1 = smem + SM_X1;
    float* s_x2 = smem + SM_X2;
    float* s_w  = smem + SM_W;
    unsigned* s_pk = (unsigned*)(smem + SM_PK);
    float* s_cg = smem + SM_CG;

    const int tid  = threadIdx.x;
    const int lane = tid & 31;
    const int wrp  = tid >> 5;
    const int bbase = blockIdx.x * BPB;

    // ---- cooperative staging: contiguous float4 copies ----
    {
        const float4* g1 = (const float4*)(x1 + (size_t)bbase * NM_ * C_);
        const float4* g2 = (const float4*)(x2 + (size_t)bbase * NM_ * C_);
        const float4* gw = (const float4*)(wgt + (size_t)bbase * NW_ * C_);
        float4* d1 = (float4*)s_x1;
        float4* d2 = (float4*)s_x2;
        float4* dw = (float4*)s_w;
        const int n1 = BPB * NM_ * C_ / 4;   // 3200
        const int nw = BPB * NW_ * C_ / 4;   // 7040
        #pragma unroll 4
        for (int i = tid; i < n1; i += THR) { d1[i] = g1[i]; d2[i] = g2[i]; }
        #pragma unroll 4
        for (int i = tid; i < nw; i += THR) { dw[i] = gw[i]; }
        // pack index tables (L2-resident after first block touches them)
        for (int n = tid; n < NNZ_; n += THR) {
            unsigned p = (unsigned)M1[n] | ((unsigned)M2[n] << 8)
                       | ((unsigned)Li[n] << 16) | ((unsigned)Mo[n] << 24);
            s_pk[n] = p;
            s_cg[n] = cg[n];
        }
    }
    __syncthreads();

    // ---- per-warp: one batch, lanes = float2 channel pairs ----
    const int b = bbase + wrp;
    const float2* px1 = (const float2*)(s_x1 + wrp * NM_ * C_) + lane;
    const float2* px2 = (const float2*)(s_x2 + wrp * NM_ * C_) + lane;
    const float2* pw  = (const float2*)(s_w  + wrp * NW_ * C_) + lane;
    float2* gout = (float2*)(out + (size_t)b * NM_ * C_) + lane;

    // zero prefill (rows with no entries must be 0; out is poisoned)
    #pragma unroll
    for (int m = 0; m < NM_; ++m)
        gout[m * 32] = make_float2(0.f, 0.f);

    float ax = 0.f, ay = 0.f;
    int cur = (int)(s_pk[0] >> 24);

    const uint4*  tp = (const uint4*)s_pk;
    const float4* tc = (const float4*)s_cg;

    #define STEP(P, CGV) do {                                          \
        unsigned p_ = (P);                                             \
        int m1_ = p_ & 255;                                            \
        int m2_ = (p_ >> 8) & 255;                                     \
        int li_ = (p_ >> 16) & 255;                                    \
        int mo_ = (int)(p_ >> 24);                                     \
        float2 a_ = px1[m1_ * 32];                                     \
        float2 b_ = px2[m2_ * 32];                                     \
        float2 w_ = pw[li_ * 32];                                      \
        if (mo_ != cur) {                                              \
            gout[cur * 32] = make_float2(ax, ay);                      \
            ax = 0.f; ay = 0.f; cur = mo_;                             \
        }                                                              \
        float cwx = (CGV) * w_.x;                                      \
        float cwy = (CGV) * w_.y;                                      \
        ax = fmaf(a_.x * b_.x, cwx, ax);                               \
        ay = fmaf(a_.y * b_.y, cwy, ay);                               \
    } while (0)

    #pragma unroll 2
    for (int q = 0; q < NNZ_ / 4; ++q) {
        uint4  p4 = tp[q];
        float4 c4 = tc[q];
        STEP(p4.x, c4.x);
        STEP(p4.y, c4.y);
        STEP(p4.z, c4.z);
        STEP(p4.w, c4.w);
    }
    // flush last segment
    gout[cur * 32] = make_float2(ax, ay);
}

extern "C" void kernel_launch(void* const* d_in, const int* in_sizes, int n_in,
                              void* d_out, int out_size)
{
    const float* x1  = (const float*)d_in[0];
    const float* x2  = (const float*)d_in[1];
    const float* wgt = (const float*)d_in[2];
    const float* cg  = (const float*)d_in[3];
    const int*   Mo  = (const int*)d_in[4];
    const int*   M1  = (const int*)d_in[5];
    const int*   M2  = (const int*)d_in[6];
    const int*   Li  = (const int*)d_in[7];
    float* out = (float*)d_out;

    cudaFuncSetAttribute(wtp_kernel, cudaFuncAttributeMaxDynamicSharedMemorySize, SM_BYTES);
    wtp_kernel<<<GRID, THR, SM_BYTES>>>(x1, x2, wgt, cg, Mo, M1, M2, Li, out);
}

// round 3
// speedup vs baseline: 1.3956x; 1.3956x over previous
#include <cuda_runtime.h>
#include <cstdint>

// Problem constants
#define B_    4096
#define NM_   25
#define C_    64
#define NNZ_  1000
#define NW_   55
#define NNZP_ 1024          // padded (8 warps x 128 entries)
#define EPW_  128           // entries per warp

#define THR   256           // 8 warps/CTA, 1 batch/CTA
#define GRID  B_            // 4096 CTAs

// SMEM layout (floats)
#define SM_X1 0
#define SM_X2 (SM_X1 + NM_*C_)        // 1600
#define SM_W  (SM_X2 + NM_*C_)        // 3200
#define SM_PK (SM_W  + NW_*C_)        // 6720
#define SM_CG (SM_PK + NNZP_)         // 7744
#define SM_FLOATS (SM_CG + NNZP_)     // 8768
#define SM_BYTES  (SM_FLOATS * 4)     // 35072

__global__ __launch_bounds__(THR, 5)
void wtp_kernel(const float* __restrict__ x1,
                const float* __restrict__ x2,
                const float* __restrict__ wgt,
                const float* __restrict__ cg,
                const int* __restrict__ Mo,
                const int* __restrict__ M1,
                const int* __restrict__ M2,
                const int* __restrict__ Li,
                float* __restrict__ out)
{
    extern __shared__ float smem[];
    float*    s_x1 = smem + SM_X1;
    float*    s_x2 = smem + SM_X2;
    float*    s_w  = smem + SM_W;
    unsigned* s_pk = (unsigned*)(smem + SM_PK);
    float*    s_cg = smem + SM_CG;

    const int tid  = threadIdx.x;
    const int lane = tid & 31;
    const int wrp  = tid >> 5;
    const int b    = blockIdx.x;

    // ---- stage one batch (coalesced float4) + packed tables ----
    {
        const float4* g1 = (const float4*)(x1 + (size_t)b * NM_ * C_);
        const float4* g2 = (const float4*)(x2 + (size_t)b * NM_ * C_);
        const float4* gw = (const float4*)(wgt + (size_t)b * NW_ * C_);
        float4* d1 = (float4*)s_x1;
        float4* d2 = (float4*)s_x2;
        float4* dw = (float4*)s_w;
        #pragma unroll 2
        for (int i = tid; i < NM_*C_/4; i += THR) { d1[i] = g1[i]; d2[i] = g2[i]; }
        #pragma unroll 4
        for (int i = tid; i < NW_*C_/4; i += THR) { dw[i] = gw[i]; }
        const unsigned mo_last = (unsigned)Mo[NNZ_ - 1] << 24;
        for (int n = tid; n < NNZP_; n += THR) {
            if (n < NNZ_) {
                s_pk[n] = (unsigned)M1[n] | ((unsigned)M2[n] << 8)
                        | ((unsigned)Li[n] << 16) | ((unsigned)Mo[n] << 24);
                s_cg[n] = cg[n];
            } else {
                // dummy: cg=0, mo = last real mo (no spurious segment)
                s_pk[n] = mo_last;
                s_cg[n] = 0.f;
            }
        }
    }
    __syncthreads();

    // ---- per-warp: 128 entries of this batch, lanes = float2 channel pairs ----
    const float2* px1 = (const float2*)s_x1 + lane;
    const float2* px2 = (const float2*)s_x2 + lane;
    const float2* pw  = (const float2*)s_w  + lane;
    float* outb = out + (size_t)b * NM_ * C_;
    float2* gout = (float2*)outb + lane;   // gout[m*32] = row m, this lane's pair

    const int e0 = wrp * EPW_;
    const uint4*  tp = (const uint4*)(s_pk + e0);
    const float4* tc = (const float4*)(s_cg + e0);

    float ax = 0.f, ay = 0.f;
    int  cur   = (int)(s_pk[e0] >> 24);
    int  first = 1;

    #define STEP(P, CGV) do {                                           \
        unsigned p_ = (P);                                              \
        int m1_ = p_ & 255;                                             \
        int m2_ = (p_ >> 8) & 255;                                      \
        int li_ = (p_ >> 16) & 255;                                     \
        int mo_ = (int)(p_ >> 24);                                      \
        float2 a_ = px1[m1_ * 32];                                      \
        float2 b_ = px2[m2_ * 32];                                      \
        float2 w_ = pw[li_ * 32];                                       \
        if (mo_ != cur) {  /* warp-uniform, rarely taken */             \
            if (first) {                                                \
                atomicAdd(&outb[cur * C_ + lane * 2    ], ax);          \
                atomicAdd(&outb[cur * C_ + lane * 2 + 1], ay);          \
                first = 0;                                              \
            } else {                                                    \
                gout[cur * 32] = make_float2(ax, ay);                   \
            }                                                           \
            ax = 0.f; ay = 0.f; cur = mo_;                              \
        }                                                               \
        ax = fmaf(a_.x * b_.x, (CGV) * w_.x, ax);                       \
        ay = fmaf(a_.y * b_.y, (CGV) * w_.y, ay);                       \
    } while (0)

    #pragma unroll 4
    for (int q = 0; q < EPW_ / 4; ++q) {
        uint4  p4 = tp[q];   // broadcast LDS.128
        float4 c4 = tc[q];
        STEP(p4.x, c4.x);
        STEP(p4.y, c4.y);
        STEP(p4.z, c4.z);
        STEP(p4.w, c4.w);
    }
    // final segment: may straddle next warp's range -> atomic
    atomicAdd(&outb[cur * C_ + lane * 2    ], ax);
    atomicAdd(&outb[cur * C_ + lane * 2 + 1], ay);
}

extern "C" void kernel_launch(void* const* d_in, const int* in_sizes, int n_in,
                              void* d_out, int out_size)
{
    const float* x1  = (const float*)d_in[0];
    const float* x2  = (const float*)d_in[1];
    const float* wgt = (const float*)d_in[2];
    const float* cg  = (const float*)d_in[3];
    const int*   Mo  = (const int*)d_in[4];
    const int*   M1  = (const int*)d_in[5];
    const int*   M2  = (const int*)d_in[6];
    const int*   Li  = (const int*)d_in[7];
    float* out = (float*)d_out;

    cudaMemsetAsync(d_out, 0, (size_t)out_size * sizeof(float), 0);
    cudaFuncSetAttribute(wtp_kernel, cudaFuncAttributeMaxDynamicSharedMemorySize, SM_BYTES);
    wtp_kernel<<<GRID, THR, SM_BYTES>>>(x1, x2, wgt, cg, Mo, M1, M2, Li, out);
}